// round 13
// baseline (speedup 1.0000x reference)
#include <cuda_runtime.h>
#include <math.h>

// -------------------------------------------------------------------------
// MultiTaskLoss, single fused kernel (v3 resubmit after 2x infra failure).
// Det path is register-lean (#pragma unroll 1 on box/class loops, shared
// box table) so the WHOLE kernel naturally fits ~32 regs -> seg path keeps
// occ=8 and full HBM bandwidth; det blocks (97) hide under the 168MB seg
// stream. Last-arriving block reduces all partials in double, writes out.
// -------------------------------------------------------------------------

#define DET_BLOCKS  96
#define CLS_BID     DET_BLOCKS
#define SEG_BASE    (DET_BLOCKS + 1)
#define SEG_BLOCKS  2048
#define GRID_BLOCKS (SEG_BASE + SEG_BLOCKS)    // 2145

__device__ float g_part[GRID_BLOCKS];
__device__ int   g_counter = 0;

// ---------------- helpers ----------------

__device__ __forceinline__ float bce_logits_f(float x, float y) {
    return fmaxf(x, 0.f) - x * y + __logf(1.f + __expf(-fabsf(x)));
}

__device__ __forceinline__ float focal_term(float x, float t) {
    float e = __expf(-fabsf(x));
    float inv1e = 1.f / (1.f + e);
    float p = (x >= 0.f) ? inv1e : e * inv1e;
    float ce = fmaxf(x, 0.f) - x * t + __logf(1.f + e);
    float pt = p * t + (1.f - p) * (1.f - t);
    float at = 0.25f * t + 0.75f * (1.f - t);
    float u = 1.f - pt;
    return at * u * u * ce;
}

__device__ __forceinline__ float block_reduce_f(float v, float* sh) {
    #pragma unroll
    for (int o = 16; o > 0; o >>= 1) v += __shfl_down_sync(0xffffffffu, v, o);
    int lane = threadIdx.x & 31, wid = threadIdx.x >> 5;
    int nw = blockDim.x >> 5;
    if (lane == 0) sh[wid] = v;
    __syncthreads();
    float r = 0.f;
    if (wid == 0) {
        r = (lane < nw) ? sh[lane] : 0.f;
        #pragma unroll
        for (int o = 16; o > 0; o >>= 1) r += __shfl_down_sync(0xffffffffu, r, o);
    }
    __syncthreads();
    return r;
}

__device__ __forceinline__ int block_reduce_i(int v, int* sh) {
    #pragma unroll
    for (int o = 16; o > 0; o >>= 1) v += __shfl_down_sync(0xffffffffu, v, o);
    int lane = threadIdx.x & 31, wid = threadIdx.x >> 5;
    int nw = blockDim.x >> 5;
    if (lane == 0) sh[wid] = v;
    __syncthreads();
    int r = 0;
    if (wid == 0) {
        r = (lane < nw) ? sh[lane] : 0;
        #pragma unroll
        for (int o = 16; o > 0; o >>= 1) r += __shfl_down_sync(0xffffffffu, r, o);
    }
    __syncthreads();
    return r;
}

// ---------------- det role (register-lean: unroll 1 everywhere) ----------

__device__ float det_block(int bid,
    const float* __restrict__ cls0, const float* __restrict__ cls1, const float* __restrict__ cls2,
    const float* __restrict__ reg0, const float* __restrict__ reg1, const float* __restrict__ reg2,
    const float* __restrict__ cen0, const float* __restrict__ cen1, const float* __restrict__ cen2,
    const float* __restrict__ boxes, const int* __restrict__ labels,
    float* shf, int* shi) {

    const int s = bid % 3;
    const int b = bid / 3;

    const float* cls; const float* reg; const float* cen;
    int H; float stride;
    if (s == 0)      { cls = cls0; reg = reg0; cen = cen0; H = 64; stride = 8.f;  }
    else if (s == 1) { cls = cls1; reg = reg1; cen = cen1; H = 32; stride = 16.f; }
    else             { cls = cls2; reg = reg2; cen = cen2; H = 16; stride = 32.f; }
    const int W = H;
    const int L = H * W;

    __shared__ float sx0[20], sy0[20], sx1[20], sy1[20], sarea[20];
    __shared__ int   slab[20];

    if (threadIdx.x < 20) {
        int j = threadIdx.x;
        const float* bx = boxes + ((long)b * 20 + j) * 4;
        float cx = bx[0] * 512.f, cy = bx[1] * 512.f;
        float wd = bx[2] * 512.f, ht = bx[3] * 512.f;
        float x0 = cx - wd * 0.5f, y0 = cy - ht * 0.5f;
        float x1 = cx + wd * 0.5f, y1 = cy + ht * 0.5f;
        sx0[j] = x0; sy0[j] = y0; sx1[j] = x1; sy1[j] = y1;
        sarea[j] = (x1 - x0) * (y1 - y0);
        slab[j]  = labels[(long)b * 20 + j];
    }
    __syncthreads();

    const float inv_stride = 1.f / stride;
    float cls_sum = 0.f, reg_sum = 0.f, cen_sum = 0.f;
    int npos = 0;

    #pragma unroll 1
    for (int loc = threadIdx.x; loc < L; loc += blockDim.x) {
        int h = loc / W;
        int w = loc - h * W;
        float lx = ((float)w + 0.5f) * stride;
        float ly = ((float)h + 0.5f) * stride;

        // argmin over inside boxes (first-minimum tie-break = jnp.argmin)
        int   bj = -1;
        float barea = INFINITY;
        #pragma unroll 1
        for (int j = 0; j < 20; j++) {
            float l  = lx - sx0[j];
            float t  = ly - sy0[j];
            float r  = sx1[j] - lx;
            float bt = sy1[j] - ly;
            float mn = fminf(fminf(l, t), fminf(r, bt));
            if (mn > 0.f && sarea[j] < barea) { barea = sarea[j]; bj = j; }
        }
        int ct = (bj >= 0) ? slab[bj] : -1;

        // focal over 4 classes (channels 1..4 of 5-channel logits)
        const float* clsb = cls + ((long)b * 5 + 1) * L + loc;
        #pragma unroll 1
        for (int c = 0; c < 4; c++) {
            float x = clsb[(long)c * L];
            cls_sum += focal_term(x, (c == ct) ? 1.f : 0.f);
        }

        if (bj >= 0) {
            npos++;
            float rt0 = (lx - sx0[bj]) * inv_stride;
            float rt1 = (ly - sy0[bj]) * inv_stride;
            float rt2 = (sx1[bj] - lx) * inv_stride;
            float rt3 = (sy1[bj] - ly) * inv_stride;

            const float* rb = reg + (long)b * 4 * L + loc;
            float sl = 0.f;
            {
                float d, ad;
                d = rb[0]          - rt0; ad = fabsf(d); sl += (ad < 1.f) ? 0.5f*d*d : (ad - 0.5f);
                d = rb[(long)L]    - rt1; ad = fabsf(d); sl += (ad < 1.f) ? 0.5f*d*d : (ad - 0.5f);
                d = rb[(long)2*L]  - rt2; ad = fabsf(d); sl += (ad < 1.f) ? 0.5f*d*d : (ad - 0.5f);
                d = rb[(long)3*L]  - rt3; ad = fabsf(d); sl += (ad < 1.f) ? 0.5f*d*d : (ad - 0.5f);
            }
            reg_sum += sl * 0.25f;

            const float eps = 1e-6f;
            float mnlr = fminf(rt0, rt2), mxlr = fmaxf(rt0, rt2);
            float mntb = fminf(rt1, rt3), mxtb = fmaxf(rt1, rt3);
            float c2 = (mnlr / (mxlr + eps)) * (mntb / (mxtb + eps));
            c2 = fminf(fmaxf(c2, 0.f), 1.f);
            float cent_t = sqrtf(c2);
            cen_sum += bce_logits_f(cen[(long)b * L + loc], cent_t);
        }
    }

    float cls_tot = block_reduce_f(cls_sum, shf);
    float reg_tot = block_reduce_f(reg_sum, shf);
    float cen_tot = block_reduce_f(cen_sum, shf);
    int   np_tot  = block_reduce_i(npos, shi);

    float cls_l = cls_tot / (float)(L * 4);
    float reg_l = (np_tot > 0) ? reg_tot / (float)np_tot : 0.f;
    float cen_l = (np_tot > 0) ? cen_tot / (float)np_tot : 0.f;
    return (cls_l + reg_l + cen_l) * (1.f / 96.f);
}

// ---------------- clspred role ----------------

__device__ float cls_block(const float* __restrict__ pred,
                           const int*   __restrict__ target, float* sh) {
    float acc = 0.f;
    #pragma unroll 1
    for (int i = threadIdx.x; i < 320; i += blockDim.x) {
        int bb = i / 10;
        int c  = i - bb * 10;
        acc += focal_term(pred[i], (target[bb] == c) ? 1.f : 0.f);
    }
    float tot = block_reduce_f(acc, sh);
    return tot * (0.5f / 320.f);
}

// ---------------- seg role (plain loads) ----------------

__device__ float seg_block(int sbid,
                           const float* __restrict__ logits,
                           const int*   __restrict__ mask, float* sh) {
    const int NV = 32 * 65536;

    float acc = 0.f;
    #pragma unroll 1
    for (int v = sbid * blockDim.x + threadIdx.x; v < NV;
         v += SEG_BLOCKS * blockDim.x) {
        int b = v >> 16;
        int r = v & 0xFFFF;
        int4 m4 = reinterpret_cast<const int4*>(mask)[((long)b << 16) + r];
        float y0 = (float)m4.x, y1 = (float)m4.y, y2 = (float)m4.z, y3 = (float)m4.w;
        long base = ((long)b << 18) + r;
        #pragma unroll
        for (int c = 0; c < 4; c++) {
            float4 x = reinterpret_cast<const float4*>(logits)[base + ((long)c << 16)];
            acc += bce_logits_f(x.x, y0);
            acc += bce_logits_f(x.y, y1);
            acc += bce_logits_f(x.z, y2);
            acc += bce_logits_f(x.w, y3);
        }
    }
    float tot = block_reduce_f(acc, sh);
    return tot * (1.f / 33554432.f);
}

// ---------------- fused kernel ----------------

__global__ void __launch_bounds__(256, 8) fused_kernel(
    const float* __restrict__ seg_logits, const int* __restrict__ seg_mask,
    const float* __restrict__ cls0, const float* __restrict__ cls1, const float* __restrict__ cls2,
    const float* __restrict__ reg0, const float* __restrict__ reg1, const float* __restrict__ reg2,
    const float* __restrict__ cen0, const float* __restrict__ cen1, const float* __restrict__ cen2,
    const float* __restrict__ boxes, const int* __restrict__ labels,
    const float* __restrict__ cls_pred, const int* __restrict__ cls_target,
    float* __restrict__ out) {

    __shared__ float shf[8];
    __shared__ int   shi[8];
    __shared__ bool  s_last;

    const int bid = blockIdx.x;
    float part;
    if (bid >= SEG_BASE) {
        part = seg_block(bid - SEG_BASE, seg_logits, seg_mask, shf);
    } else if (bid < DET_BLOCKS) {
        part = det_block(bid, cls0, cls1, cls2, reg0, reg1, reg2,
                         cen0, cen1, cen2, boxes, labels, shf, shi);
    } else {
        part = cls_block(cls_pred, cls_target, shf);
    }

    if (threadIdx.x == 0) {
        g_part[bid] = part;
        __threadfence();
        int arrived = atomicAdd(&g_counter, 1);
        s_last = (arrived == GRID_BLOCKS - 1);
    }
    __syncthreads();

    if (s_last) {
        __shared__ double shd[8];
        double dacc = 0.0;
        #pragma unroll 1
        for (int i = threadIdx.x; i < GRID_BLOCKS; i += blockDim.x)
            dacc += (double)g_part[i];
        #pragma unroll
        for (int o = 16; o > 0; o >>= 1) dacc += __shfl_down_sync(0xffffffffu, dacc, o);
        int lane = threadIdx.x & 31, wid = threadIdx.x >> 5;
        if (lane == 0) shd[wid] = dacc;
        __syncthreads();
        if (wid == 0) {
            double r = (lane < 8) ? shd[lane] : 0.0;
            #pragma unroll
            for (int o = 4; o > 0; o >>= 1) r += __shfl_down_sync(0xffffffffu, r, o);
            if (lane == 0) {
                out[0] = (float)r;
                g_counter = 0;          // reset for next graph replay
            }
        }
    }
}

// ---------------- launch ----------------

extern "C" void kernel_launch(void* const* d_in, const int* in_sizes, int n_in,
                              void* d_out, int out_size) {
    const float* seg_logits = (const float*)d_in[0];
    const int*   seg_mask   = (const int*)  d_in[1];
    const float* cls_s0     = (const float*)d_in[2];
    const float* cls_s1     = (const float*)d_in[3];
    const float* cls_s2     = (const float*)d_in[4];
    const float* reg_s0     = (const float*)d_in[5];
    const float* reg_s1     = (const float*)d_in[6];
    const float* reg_s2     = (const float*)d_in[7];
    const float* cen_s0     = (const float*)d_in[8];
    const float* cen_s1     = (const float*)d_in[9];
    const float* cen_s2     = (const float*)d_in[10];
    const float* boxes      = (const float*)d_in[11];
    const int*   labels     = (const int*)  d_in[12];
    const float* cls_pred   = (const float*)d_in[13];
    const int*   cls_target = (const int*)  d_in[14];
    float* out = (float*)d_out;

    fused_kernel<<<GRID_BLOCKS, 256>>>(
        seg_logits, seg_mask,
        cls_s0, cls_s1, cls_s2,
        reg_s0, reg_s1, reg_s2,
        cen_s0, cen_s1, cen_s2,
        boxes, labels, cls_pred, cls_target, out);
}

// round 14
// speedup vs baseline: 2.5419x; 2.5419x over previous
#include <cuda_runtime.h>
#include <math.h>

// -------------------------------------------------------------------------
// MultiTaskLoss, single fused kernel v4.
// Det: ONE location per thread (no per-thread loop) -> all global loads
// issue concurrently, latency hidden by TLP, tiny live set. Per-(image,
// scale) sums accumulate via int64 fixed-point atomics (deterministic).
// Seg: proven 32-reg float4 streaming path.
// Last-arriving block combines everything in double and writes the scalar.
// -------------------------------------------------------------------------

#define DET_BLOCKS  672              // 32 images * (16 + 4 + 1) chunks
#define CLS_BID     DET_BLOCKS
#define SEG_BASE    (DET_BLOCKS + 1)
#define SEG_BLOCKS  2048
#define GRID_BLOCKS (SEG_BASE + SEG_BLOCKS)   // 2721

#define FP_SCALE 268435456.0         // 2^28 fixed-point scale

__device__ float              g_seg_part[SEG_BLOCKS];
__device__ float              g_cls_part;
__device__ unsigned long long g_det_acc[96 * 3];   // (b*3+s)*3 layout: [idx*3+k]
__device__ int                g_det_npos[96];
__device__ int                g_counter = 0;

// ---------------- helpers ----------------

__device__ __forceinline__ float bce_logits_f(float x, float y) {
    return fmaxf(x, 0.f) - x * y + __logf(1.f + __expf(-fabsf(x)));
}

__device__ __forceinline__ float focal_term(float x, float t) {
    float e = __expf(-fabsf(x));
    float inv1e = 1.f / (1.f + e);
    float p = (x >= 0.f) ? inv1e : e * inv1e;
    float ce = fmaxf(x, 0.f) - x * t + __logf(1.f + e);
    float pt = p * t + (1.f - p) * (1.f - t);
    float at = 0.25f * t + 0.75f * (1.f - t);
    float u = 1.f - pt;
    return at * u * u * ce;
}

__device__ __forceinline__ float block_reduce_f(float v, float* sh) {
    #pragma unroll
    for (int o = 16; o > 0; o >>= 1) v += __shfl_down_sync(0xffffffffu, v, o);
    int lane = threadIdx.x & 31, wid = threadIdx.x >> 5;
    if (lane == 0) sh[wid] = v;
    __syncthreads();
    float r = 0.f;
    if (wid == 0) {
        r = (lane < 8) ? sh[lane] : 0.f;
        #pragma unroll
        for (int o = 4; o > 0; o >>= 1) r += __shfl_down_sync(0xffffffffu, r, o);
    }
    __syncthreads();
    return r;                           // valid on thread 0
}

__device__ __forceinline__ int block_reduce_i(int v, int* sh) {
    #pragma unroll
    for (int o = 16; o > 0; o >>= 1) v += __shfl_down_sync(0xffffffffu, v, o);
    int lane = threadIdx.x & 31, wid = threadIdx.x >> 5;
    if (lane == 0) sh[wid] = v;
    __syncthreads();
    int r = 0;
    if (wid == 0) {
        r = (lane < 8) ? sh[lane] : 0;
        #pragma unroll
        for (int o = 4; o > 0; o >>= 1) r += __shfl_down_sync(0xffffffffu, r, o);
    }
    __syncthreads();
    return r;
}

// ---------------- det role: one location per thread ----------------

__device__ void det_block(int d,
    const float* __restrict__ cls0, const float* __restrict__ cls1, const float* __restrict__ cls2,
    const float* __restrict__ reg0, const float* __restrict__ reg1, const float* __restrict__ reg2,
    const float* __restrict__ cen0, const float* __restrict__ cen1, const float* __restrict__ cen2,
    const float* __restrict__ boxes, const int* __restrict__ labels,
    float* shf, int* shi) {

    const int b = d / 21;
    const int t = d - b * 21;

    const float* cls; const float* reg; const float* cen;
    int s, chunk, logW; float stride;
    if (t < 16)      { s = 0; chunk = t;      cls = cls0; reg = reg0; cen = cen0; logW = 6; stride = 8.f;  }
    else if (t < 20) { s = 1; chunk = t - 16; cls = cls1; reg = reg1; cen = cen1; logW = 5; stride = 16.f; }
    else             { s = 2; chunk = 0;      cls = cls2; reg = reg2; cen = cen2; logW = 4; stride = 32.f; }
    const int W = 1 << logW;
    const int L = W * W;

    __shared__ float sx0[20], sy0[20], sx1[20], sy1[20], sarea[20];
    __shared__ int   slab[20];

    if (threadIdx.x < 20) {
        int j = threadIdx.x;
        const float* bx = boxes + ((long)b * 20 + j) * 4;
        float cx = bx[0] * 512.f, cy = bx[1] * 512.f;
        float wd = bx[2] * 512.f, ht = bx[3] * 512.f;
        sx0[j] = cx - wd * 0.5f; sy0[j] = cy - ht * 0.5f;
        sx1[j] = cx + wd * 0.5f; sy1[j] = cy + ht * 0.5f;
        sarea[j] = wd * ht;
        slab[j]  = labels[(long)b * 20 + j];
    }
    __syncthreads();

    const int loc = chunk * 256 + threadIdx.x;   // always < L (chunks tile L exactly)
    const int h = loc >> logW;
    const int w = loc & (W - 1);
    const float lx = ((float)w + 0.5f) * stride;
    const float ly = ((float)h + 0.5f) * stride;

    // ---- issue ALL global loads up front (concurrent, TLP-hidden) ----
    const float* clsb = cls + ((long)b * 5 + 1) * L + loc;
    float c0 = clsb[0];
    float c1 = clsb[(long)L];
    float c2 = clsb[(long)2 * L];
    float c3 = clsb[(long)3 * L];
    const float* rb = reg + (long)b * 4 * L + loc;
    float r0 = rb[0];
    float r1 = rb[(long)L];
    float r2 = rb[(long)2 * L];
    float r3 = rb[(long)3 * L];
    float cv = cen[(long)b * L + loc];

    // ---- argmin over inside boxes (first-min tie-break = jnp.argmin) ----
    int   bj = -1;
    float barea = INFINITY;
    #pragma unroll 1
    for (int j = 0; j < 20; j++) {
        float l  = lx - sx0[j];
        float tt = ly - sy0[j];
        float r  = sx1[j] - lx;
        float bt = sy1[j] - ly;
        float mn = fminf(fminf(l, tt), fminf(r, bt));
        if (mn > 0.f && sarea[j] < barea) { barea = sarea[j]; bj = j; }
    }
    const int ct = (bj >= 0) ? slab[bj] : -1;

    // ---- focal over 4 classes ----
    float cls_sum = focal_term(c0, (ct == 0) ? 1.f : 0.f)
                  + focal_term(c1, (ct == 1) ? 1.f : 0.f)
                  + focal_term(c2, (ct == 2) ? 1.f : 0.f)
                  + focal_term(c3, (ct == 3) ? 1.f : 0.f);

    // ---- positive-location terms ----
    float reg_sum = 0.f, cen_sum = 0.f;
    int   np = 0;
    if (bj >= 0) {
        np = 1;
        const float inv_stride = 1.f / stride;
        float rt0 = (lx - sx0[bj]) * inv_stride;
        float rt1 = (ly - sy0[bj]) * inv_stride;
        float rt2 = (sx1[bj] - lx) * inv_stride;
        float rt3 = (sy1[bj] - ly) * inv_stride;

        float d0 = r0 - rt0, a0 = fabsf(d0);
        float d1 = r1 - rt1, a1 = fabsf(d1);
        float d2 = r2 - rt2, a2 = fabsf(d2);
        float d3 = r3 - rt3, a3 = fabsf(d3);
        float sl = ((a0 < 1.f) ? 0.5f*d0*d0 : (a0 - 0.5f))
                 + ((a1 < 1.f) ? 0.5f*d1*d1 : (a1 - 0.5f))
                 + ((a2 < 1.f) ? 0.5f*d2*d2 : (a2 - 0.5f))
                 + ((a3 < 1.f) ? 0.5f*d3*d3 : (a3 - 0.5f));
        reg_sum = sl * 0.25f;

        const float eps = 1e-6f;
        float mnlr = fminf(rt0, rt2), mxlr = fmaxf(rt0, rt2);
        float mntb = fminf(rt1, rt3), mxtb = fmaxf(rt1, rt3);
        float c2v = (mnlr / (mxlr + eps)) * (mntb / (mxtb + eps));
        c2v = fminf(fmaxf(c2v, 0.f), 1.f);
        cen_sum = bce_logits_f(cv, sqrtf(c2v));
    }

    // ---- block reduce + deterministic fixed-point atomics ----
    float cls_tot = block_reduce_f(cls_sum, shf);
    float reg_tot = block_reduce_f(reg_sum, shf);
    float cen_tot = block_reduce_f(cen_sum, shf);
    int   np_tot  = block_reduce_i(np, shi);

    if (threadIdx.x == 0) {
        int idx = b * 3 + s;
        atomicAdd(&g_det_acc[idx * 3 + 0],
                  (unsigned long long)(long long)__double2ll_rn((double)cls_tot * FP_SCALE));
        atomicAdd(&g_det_acc[idx * 3 + 1],
                  (unsigned long long)(long long)__double2ll_rn((double)reg_tot * FP_SCALE));
        atomicAdd(&g_det_acc[idx * 3 + 2],
                  (unsigned long long)(long long)__double2ll_rn((double)cen_tot * FP_SCALE));
        atomicAdd(&g_det_npos[idx], np_tot);
    }
}

// ---------------- clspred role ----------------

__device__ void cls_block(const float* __restrict__ pred,
                          const int*   __restrict__ target, float* sh) {
    float acc = 0.f;
    #pragma unroll 1
    for (int i = threadIdx.x; i < 320; i += 256) {
        int bb = i / 10;
        int c  = i - bb * 10;
        acc += focal_term(pred[i], (target[bb] == c) ? 1.f : 0.f);
    }
    float tot = block_reduce_f(acc, sh);
    if (threadIdx.x == 0) g_cls_part = tot * (0.5f / 320.f);
}

// ---------------- seg role (proven streaming path) ----------------

__device__ void seg_block(int sbid,
                          const float* __restrict__ logits,
                          const int*   __restrict__ mask, float* sh) {
    const int NV = 32 * 65536;

    float acc = 0.f;
    #pragma unroll 1
    for (int v = sbid * 256 + threadIdx.x; v < NV; v += SEG_BLOCKS * 256) {
        int b = v >> 16;
        int r = v & 0xFFFF;
        int4 m4 = reinterpret_cast<const int4*>(mask)[((long)b << 16) + r];
        float y0 = (float)m4.x, y1 = (float)m4.y, y2 = (float)m4.z, y3 = (float)m4.w;
        long base = ((long)b << 18) + r;
        #pragma unroll
        for (int c = 0; c < 4; c++) {
            float4 x = reinterpret_cast<const float4*>(logits)[base + ((long)c << 16)];
            acc += bce_logits_f(x.x, y0);
            acc += bce_logits_f(x.y, y1);
            acc += bce_logits_f(x.z, y2);
            acc += bce_logits_f(x.w, y3);
        }
    }
    float tot = block_reduce_f(acc, sh);
    if (threadIdx.x == 0) g_seg_part[sbid] = tot * (1.f / 33554432.f);
}

// ---------------- fused kernel ----------------

__global__ void __launch_bounds__(256, 6) fused_kernel(
    const float* __restrict__ seg_logits, const int* __restrict__ seg_mask,
    const float* __restrict__ cls0, const float* __restrict__ cls1, const float* __restrict__ cls2,
    const float* __restrict__ reg0, const float* __restrict__ reg1, const float* __restrict__ reg2,
    const float* __restrict__ cen0, const float* __restrict__ cen1, const float* __restrict__ cen2,
    const float* __restrict__ boxes, const int* __restrict__ labels,
    const float* __restrict__ cls_pred, const int* __restrict__ cls_target,
    float* __restrict__ out) {

    __shared__ float shf[8];
    __shared__ int   shi[8];
    __shared__ bool  s_last;

    const int bid = blockIdx.x;
    if (bid >= SEG_BASE) {
        seg_block(bid - SEG_BASE, seg_logits, seg_mask, shf);
    } else if (bid < DET_BLOCKS) {
        det_block(bid, cls0, cls1, cls2, reg0, reg1, reg2,
                  cen0, cen1, cen2, boxes, labels, shf, shi);
    } else {
        cls_block(cls_pred, cls_target, shf);
    }

    if (threadIdx.x == 0) {
        __threadfence();
        int arrived = atomicAdd(&g_counter, 1);
        s_last = (arrived == GRID_BLOCKS - 1);
    }
    __syncthreads();

    if (s_last) {
        // ---- final combine in double (deterministic layout) ----
        __shared__ double shd[8];
        double dacc = 0.0;

        // det: 96 (image,scale) cells, one per thread
        if (threadIdx.x < 96) {
            int i = threadIdx.x;
            int s = i - (i / 3) * 3;
            int L = (s == 0) ? 4096 : (s == 1) ? 1024 : 256;
            double cls_l = ((double)(long long)g_det_acc[i * 3 + 0]) / FP_SCALE / (double)(L * 4);
            int np = g_det_npos[i];
            double reg_l = (np > 0) ? ((double)(long long)g_det_acc[i * 3 + 1]) / FP_SCALE / (double)np : 0.0;
            double cen_l = (np > 0) ? ((double)(long long)g_det_acc[i * 3 + 2]) / FP_SCALE / (double)np : 0.0;
            dacc += (cls_l + reg_l + cen_l) * (1.0 / 96.0);
            // reset accumulators for the next graph replay
            g_det_acc[i * 3 + 0] = 0ull;
            g_det_acc[i * 3 + 1] = 0ull;
            g_det_acc[i * 3 + 2] = 0ull;
            g_det_npos[i] = 0;
        }
        // seg partials + cls term
        #pragma unroll 1
        for (int i = threadIdx.x; i < SEG_BLOCKS; i += 256)
            dacc += (double)g_seg_part[i];
        if (threadIdx.x == 0)
            dacc += (double)g_cls_part;

        #pragma unroll
        for (int o = 16; o > 0; o >>= 1) dacc += __shfl_down_sync(0xffffffffu, dacc, o);
        int lane = threadIdx.x & 31, wid = threadIdx.x >> 5;
        if (lane == 0) shd[wid] = dacc;
        __syncthreads();
        if (wid == 0) {
            double r = (lane < 8) ? shd[lane] : 0.0;
            #pragma unroll
            for (int o = 4; o > 0; o >>= 1) r += __shfl_down_sync(0xffffffffu, r, o);
            if (lane == 0) {
                out[0] = (float)r;
                g_counter = 0;          // reset for next graph replay
            }
        }
    }
}

// ---------------- launch ----------------

extern "C" void kernel_launch(void* const* d_in, const int* in_sizes, int n_in,
                              void* d_out, int out_size) {
    const float* seg_logits = (const float*)d_in[0];
    const int*   seg_mask   = (const int*)  d_in[1];
    const float* cls_s0     = (const float*)d_in[2];
    const float* cls_s1     = (const float*)d_in[3];
    const float* cls_s2     = (const float*)d_in[4];
    const float* reg_s0     = (const float*)d_in[5];
    const float* reg_s1     = (const float*)d_in[6];
    const float* reg_s2     = (const float*)d_in[7];
    const float* cen_s0     = (const float*)d_in[8];
    const float* cen_s1     = (const float*)d_in[9];
    const float* cen_s2     = (const float*)d_in[10];
    const float* boxes      = (const float*)d_in[11];
    const int*   labels     = (const int*)  d_in[12];
    const float* cls_pred   = (const float*)d_in[13];
    const int*   cls_target = (const int*)  d_in[14];
    float* out = (float*)d_out;

    fused_kernel<<<GRID_BLOCKS, 256>>>(
        seg_logits, seg_mask,
        cls_s0, cls_s1, cls_s2,
        reg_s0, reg_s1, reg_s2,
        cen_s0, cen_s1, cen_s2,
        boxes, labels, cls_pred, cls_target, out);
}